// round 4
// baseline (speedup 1.0000x reference)
#include <cuda_runtime.h>
#include <math.h>

#define D4    64            // 256 dims = 64 float4
#define C     64
#define MAXNQ 4096
#define MAXNS 8192
#define QT    16            // queries per tile
#define MB    64            // members per staged chunk
#define MAXTILES (MAXNQ/QT + C)   // 320
#define NEG  (-3.0e38f)
#define SMEM_MAIN ((QT*D4 + MB*D4) * 16)   // 80 KB dynamic

// Scratch (device globals; fully rewritten every call -> replay-safe).
__device__ float g_qn[MAXNQ];
__device__ float g_sn[MAXNS];
__device__ float g_cent[C * 256];
__device__ float g_ssum[C];
__device__ int   g_counts[C];
__device__ int   g_start[C + 1];
__device__ int   g_cidx[MAXNS];
__device__ int   g_qidx[MAXNQ];
__device__ int   g_tc[MAXTILES], g_toff[MAXTILES], g_tcnt[MAXTILES];
__device__ int   g_ntiles;
__device__ float g_res[MAXNQ];

__device__ __forceinline__ float warp_sum(float v) {
#pragma unroll
    for (int o = 16; o; o >>= 1) v += __shfl_xor_sync(0xffffffffu, v, o);
    return v;
}

// Packed dual-FMA: d.lo += a.lo*b.lo ; d.hi += a.hi*b.hi   (Blackwell f32x2)
__device__ __forceinline__ void fma2(unsigned long long& d,
                                     unsigned long long a, unsigned long long b) {
    asm("fma.rn.f32x2 %0, %1, %2, %0;" : "+l"(d) : "l"(a), "l"(b));
}
__device__ __forceinline__ float hsum2(unsigned long long v) {
    float lo, hi;
    asm("mov.b64 {%0, %1}, %2;" : "=f"(lo), "=f"(hi) : "l"(v));
    return lo + hi;
}

// ---------------------------------------------------------------------------
// Kernel A: fused prep. Block 0: class lists + tile schedule.
// Blocks >=1: row sq-norms for xq and xs (one warp per row).
// ---------------------------------------------------------------------------
__global__ void kA(const float* __restrict__ xq, const float* __restrict__ xs,
                   const int* __restrict__ ys, const int* __restrict__ yq,
                   int Nq, int Ns) {
    if (blockIdx.x == 0) {
        __shared__ int wh[8][C], wqh[8][C];
        __shared__ int cnt[C], off[C], qcnt[C], qoff[C];
        int tid = threadIdx.x, w = tid >> 5;
        for (int i = tid; i < 8 * C; i += 256) { (&wh[0][0])[i] = 0; (&wqh[0][0])[i] = 0; }
        __syncthreads();
        for (int j = tid; j < Ns; j += 256) atomicAdd(&wh[w][ys[j]], 1);
        for (int i = tid; i < Nq; i += 256) atomicAdd(&wqh[w][yq[i]], 1);
        __syncthreads();
        if (tid < C) {
            int s = 0, sq = 0;
#pragma unroll
            for (int r = 0; r < 8; r++) { s += wh[r][tid]; sq += wqh[r][tid]; }
            cnt[tid] = s; qcnt[tid] = sq;
        }
        __syncthreads();
        if (tid == 0) {
            int acc = 0, qacc = 0, nt = 0;
            for (int c = 0; c < C; c++) {
                g_counts[c] = cnt[c]; g_start[c] = acc; off[c] = acc; acc += cnt[c];
                qoff[c] = qacc;
                for (int t = 0; t < qcnt[c]; t += QT) {
                    g_tc[nt] = c; g_toff[nt] = qacc + t;
                    g_tcnt[nt] = min(QT, qcnt[c] - t); nt++;
                }
                qacc += qcnt[c];
            }
            g_start[C] = acc; g_ntiles = nt;
        }
        __syncthreads();
        for (int j = tid; j < Ns; j += 256) { int p = atomicAdd(&off[ys[j]], 1);  g_cidx[p] = j; }
        for (int i = tid; i < Nq; i += 256) { int p = atomicAdd(&qoff[yq[i]], 1); g_qidx[p] = i; }
    } else {
        int warp = (blockIdx.x - 1) * 8 + (threadIdx.x >> 5);
        int lane = threadIdx.x & 31;
        if (warp >= Nq + Ns) return;
        const float4* r4 = (const float4*)((warp < Nq) ? (xq + (size_t)warp * 256)
                                                       : (xs + (size_t)(warp - Nq) * 256));
        float4 a = r4[lane], b = r4[lane + 32];
        float s = a.x*a.x + a.y*a.y + a.z*a.z + a.w*a.w
                + b.x*b.x + b.y*b.y + b.z*b.z + b.w*b.w;
        s = warp_sum(s);
        if (lane == 0) { if (warp < Nq) g_qn[warp] = s; else g_sn[warp - Nq] = s; }
    }
}

// ---------------------------------------------------------------------------
// Kernel B: per-class centroids + sum of member sq-norms. Grid (C,2), 8x unroll.
// ---------------------------------------------------------------------------
__global__ void k_cent(const float* __restrict__ xs) {
    int c = blockIdx.x, tid = threadIdx.x;
    int dim = blockIdx.y * 128 + tid;
    int s0 = g_start[c], s1 = g_start[c + 1];
    float acc = 0.0f;
    int m = s0;
    for (; m + 7 < s1; m += 8) {
        float v0 = xs[(size_t)g_cidx[m]   * 256 + dim];
        float v1 = xs[(size_t)g_cidx[m+1] * 256 + dim];
        float v2 = xs[(size_t)g_cidx[m+2] * 256 + dim];
        float v3 = xs[(size_t)g_cidx[m+3] * 256 + dim];
        float v4 = xs[(size_t)g_cidx[m+4] * 256 + dim];
        float v5 = xs[(size_t)g_cidx[m+5] * 256 + dim];
        float v6 = xs[(size_t)g_cidx[m+6] * 256 + dim];
        float v7 = xs[(size_t)g_cidx[m+7] * 256 + dim];
        acc += ((v0 + v1) + (v2 + v3)) + ((v4 + v5) + (v6 + v7));
    }
    for (; m < s1; m++) acc += xs[(size_t)g_cidx[m] * 256 + dim];
    g_cent[c * 256 + dim] = acc;

    if (blockIdx.y == 0) {
        float ss = 0.0f;
        for (int k = s0 + tid; k < s1; k += 128) ss += g_sn[g_cidx[k]];
        __shared__ float sred[128];
        sred[tid] = ss; __syncthreads();
        for (int s = 64; s; s >>= 1) { if (tid < s) sred[tid] += sred[tid + s]; __syncthreads(); }
        if (tid == 0) g_ssum[c] = sred[0];
    }
}

// ---------------------------------------------------------------------------
// Kernel C: main. 64 threads = 2 warps. Warp w owns queries 8w..8w+7;
// lane owns members 2l,2l+1. 8x2 register tile of f32x2 accumulators.
// 80 KB smem -> 2 CTAs/SM.
// ---------------------------------------------------------------------------
__global__ void __launch_bounds__(64)
k_main(const float* __restrict__ xq, const float* __restrict__ xs,
       const int* __restrict__ pos) {
    int b = blockIdx.x;
    if (b >= g_ntiles) return;

    extern __shared__ float4 dsm[];
    float4* s_q4 = dsm;                  // QT rows x 64 float4
    float4* s_m4 = dsm + QT * D4;        // MB rows x 64 float4, XOR-swizzled
    __shared__ float s_lorig[QT];
    __shared__ float s_msn[MB];
    __shared__ int   s_mj[MB];

    int t = threadIdx.x, w = t >> 5, l = t & 31;
    int c    = g_tc[b];
    int qoff = g_toff[b];
    int qcnt = g_tcnt[b];
    float v  = (g_counts[c] > 1) ? -1000.0f : 0.0f;

    // Load 16 query rows (8 per warp) + metadata.
    float qn[8]; int p[8];
#pragma unroll
    for (int k = 0; k < 8; k++) {
        int ql = 8 * w + k;
        int qi = g_qidx[qoff + min(ql, qcnt - 1)];
        const float4* src = (const float4*)xq + (size_t)qi * D4;
        s_q4[ql * D4 + l]      = src[l];
        s_q4[ql * D4 + l + 32] = src[l + 32];
        qn[k] = g_qn[qi];
        p[k]  = pos[qi];
    }

    int s0 = g_start[c];
    int Mc = g_start[c + 1] - s0;

    float pm[8], ps[8];
#pragma unroll
    for (int k = 0; k < 8; k++) { pm[k] = NEG; ps[k] = 0.0f; }

    const int m0 = 2 * l, m1 = 2 * l + 1;
    const int sig = l & 7;
    const ulonglong2* mr0 = (const ulonglong2*)(s_m4 + m0 * D4);
    const ulonglong2* mr1 = (const ulonglong2*)(s_m4 + m1 * D4);

    // ---- member chunks: positive (in-class) logsumexp ----
    for (int base = 0; base < Mc; base += MB) {
        int nm = min(MB, Mc - base);
        __syncthreads();
        for (int r = 0; r < 32; r++) {
            int m = 2 * r + w;
            if (m < nm) {
                int j = g_cidx[s0 + base + m];
                int sg = (m >> 1) & 7;
                const float4* src = (const float4*)xs + (size_t)j * D4;
                s_m4[m * D4 + (l ^ sg)]        = src[l];
                s_m4[m * D4 + ((l + 32) ^ sg)] = src[l + 32];
                if (l == 0) { s_mj[m] = j; s_msn[m] = g_sn[j]; }
            } else if (l == 0) s_mj[m] = -1;
        }
        __syncthreads();

        unsigned long long acc[8][2];
#pragma unroll
        for (int k = 0; k < 8; k++) { acc[k][0] = 0ull; acc[k][1] = 0ull; }

#pragma unroll 4
        for (int d = 0; d < D4; d++) {
            int cc = d ^ sig;
            ulonglong2 A = mr0[cc];
            ulonglong2 B = mr1[cc];
#pragma unroll
            for (int k = 0; k < 8; k++) {
                ulonglong2 Q = ((const ulonglong2*)(s_q4 + (8 * w + k) * D4))[d];
                fma2(acc[k][0], Q.x, A.x);
                fma2(acc[k][0], Q.y, A.y);
                fma2(acc[k][1], Q.x, B.x);
                fma2(acc[k][1], Q.y, B.y);
            }
        }

        int   j0 = s_mj[m0],  j1 = s_mj[m1];
        float sn0 = s_msn[m0], sn1 = s_msn[m1];
#pragma unroll
        for (int k = 0; k < 8; k++) {
            float d0 = hsum2(acc[k][0]);
            float d1 = hsum2(acc[k][1]);
            float r0 = -0.5f * fmaxf(qn[k] + sn0 - 2.0f * d0, 0.0f);
            float r1 = -0.5f * fmaxf(qn[k] + sn1 - 2.0f * d1, 0.0f);
            float l0 = (j0 < 0) ? NEG : ((j0 == p[k]) ? v : r0);
            float l1 = (j1 < 0) ? NEG : ((j1 == p[k]) ? v : r1);
            if (j0 >= 0 && j0 == p[k]) s_lorig[8 * w + k] = r0;
            if (j1 >= 0 && j1 == p[k]) s_lorig[8 * w + k] = r1;
            float mx = fmaxf(pm[k], fmaxf(l0, l1));
            if (mx > -1e37f) {
                ps[k] = ps[k] * expf(pm[k] - mx) + expf(l0 - mx) + expf(l1 - mx);
                pm[k] = mx;
            }
        }
    }

    // warp-reduce positive logsumexp
    float posl[8];
#pragma unroll
    for (int k = 0; k < 8; k++) {
        float m = pm[k], s = ps[k];
        for (int o = 16; o; o >>= 1) {
            float om = __shfl_xor_sync(0xffffffffu, m, o);
            float os = __shfl_xor_sync(0xffffffffu, s, o);
            float mx = fmaxf(m, om);
            if (mx > -1e37f) s = s * expf(m - mx) + os * expf(om - mx);
            m = mx;
        }
        posl[k] = m + logf(s);
    }

    // ---- centroid chunk: negative term (closed form + diagonal correction) ----
    __syncthreads();
    for (int r = 0; r < 32; r++) {
        int m = 2 * r + w;
        int sg = (m >> 1) & 7;
        const float4* src = (const float4*)g_cent + (size_t)m * D4;
        s_m4[m * D4 + (l ^ sg)]        = src[l];
        s_m4[m * D4 + ((l + 32) ^ sg)] = src[l + 32];
    }
    __syncthreads();

    {
        unsigned long long acc[8][2];
#pragma unroll
        for (int k = 0; k < 8; k++) { acc[k][0] = 0ull; acc[k][1] = 0ull; }

#pragma unroll 4
        for (int d = 0; d < D4; d++) {
            int cc = d ^ sig;
            ulonglong2 A = mr0[cc];
            ulonglong2 B = mr1[cc];
#pragma unroll
            for (int k = 0; k < 8; k++) {
                ulonglong2 Q = ((const ulonglong2*)(s_q4 + (8 * w + k) * D4))[d];
                fma2(acc[k][0], Q.x, A.x);
                fma2(acc[k][0], Q.y, A.y);
                fma2(acc[k][1], Q.x, B.x);
                fma2(acc[k][1], Q.y, B.y);
            }
        }

        float cnt0 = (float)g_counts[m0], cnt1 = (float)g_counts[m1];
        float ss0 = g_ssum[m0], ss1 = g_ssum[m1];
        bool  isc0 = (m0 == c), isc1 = (m1 == c);
#pragma unroll
        for (int k = 0; k < 8; k++) {
            float lo = s_lorig[8 * w + k];
            float x0 = -0.5f * (cnt0 * qn[k] + ss0) + hsum2(acc[k][0]);
            float x1 = -0.5f * (cnt1 * qn[k] + ss1) + hsum2(acc[k][1]);
            if (isc0) x0 += v - lo;
            if (isc1) x1 += v - lo;
            x0 /= cnt0 - (isc0 ? 1.0f : 0.0f);
            x1 /= cnt1 - (isc1 ? 1.0f : 0.0f);
            float m = fmaxf(x0, x1);
            float s = expf(x0 - m) + expf(x1 - m);
            for (int o = 16; o; o >>= 1) {
                float om = __shfl_xor_sync(0xffffffffu, m, o);
                float os = __shfl_xor_sync(0xffffffffu, s, o);
                float mx = fmaxf(m, om);
                s = s * expf(m - mx) + os * expf(om - mx);
                m = mx;
            }
            if (l == 0 && 8 * w + k < qcnt) {
                float neg = m + logf(s);
                g_res[g_qidx[qoff + 8 * w + k]] = neg - posl[k];
            }
        }
    }
}

// ---------------------------------------------------------------------------
// Kernel D: mean over queries.
// ---------------------------------------------------------------------------
__global__ void k_reduce(float* __restrict__ out, int Nq) {
    __shared__ float sred[256];
    int tid = threadIdx.x;
    float a = 0.0f;
    for (int i = tid; i < Nq; i += 256) a += g_res[i];
    sred[tid] = a; __syncthreads();
    for (int s = 128; s; s >>= 1) { if (tid < s) sred[tid] += sred[tid + s]; __syncthreads(); }
    if (tid == 0) out[0] = sred[0] / (float)Nq;
}

extern "C" void kernel_launch(void* const* d_in, const int* in_sizes, int n_in,
                              void* d_out, int out_size) {
    const float* xq  = (const float*)d_in[0];
    const int*   yq  = (const int*)  d_in[1];
    const float* xs  = (const float*)d_in[2];
    const int*   ys  = (const int*)  d_in[3];
    const int*   pos = (const int*)  d_in[4];
    int Nq = in_sizes[1];
    int Ns = in_sizes[3];

    cudaFuncSetAttribute(k_main, cudaFuncAttributeMaxDynamicSharedMemorySize, SMEM_MAIN);

    int gA = 1 + (Nq + Ns + 7) / 8;
    kA<<<gA, 256>>>(xq, xs, ys, yq, Nq, Ns);
    dim3 gc(C, 2);
    k_cent<<<gc, 128>>>(xs);
    k_main<<<MAXTILES, 64, SMEM_MAIN>>>(xq, xs, pos);
    k_reduce<<<1, 256>>>((float*)d_out, Nq);
}

// round 5
// speedup vs baseline: 1.1868x; 1.1868x over previous
#include <cuda_runtime.h>
#include <math.h>

#define D4    64            // 256 dims = 64 float4
#define C     64
#define MAXNQ 4096
#define MAXNS 8192
#define QT    32            // queries per tile
#define MB    64            // members per staged chunk
#define MAXTILES (MAXNQ/QT + C)   // 192
#define NEG  (-3.0e38f)
#define SMEM_MAIN ((QT*D4 + MB*D4) * 16)   // 96 KB dynamic

// Scratch (device globals; fully rewritten every call -> replay-safe).
__device__ float g_qn[MAXNQ];
__device__ float g_sn[MAXNS];
__device__ float g_cent[C * 256];
__device__ float g_ssum[C];
__device__ int   g_counts[C];
__device__ int   g_start[C + 1];
__device__ int   g_cidx[MAXNS];
__device__ int   g_qidx[MAXNQ];
__device__ int   g_tc[MAXTILES], g_toff[MAXTILES], g_tcnt[MAXTILES];
__device__ int   g_ntiles;

__device__ __forceinline__ float warp_sum(float v) {
#pragma unroll
    for (int o = 16; o; o >>= 1) v += __shfl_xor_sync(0xffffffffu, v, o);
    return v;
}

// Packed dual-FMA: d.lo += a.lo*b.lo ; d.hi += a.hi*b.hi   (Blackwell f32x2)
__device__ __forceinline__ void fma2(unsigned long long& d,
                                     unsigned long long a, unsigned long long b) {
    asm("fma.rn.f32x2 %0, %1, %2, %0;" : "+l"(d) : "l"(a), "l"(b));
}
__device__ __forceinline__ float hsum2(unsigned long long v) {
    float lo, hi;
    asm("mov.b64 {%0, %1}, %2;" : "=f"(lo), "=f"(hi) : "l"(v));
    return lo + hi;
}

// ---------------------------------------------------------------------------
// Kernel 1 (kPrep): block 0 = class lists + tile schedule.
// Blocks >= 1 = row sq-norms for xq and xs (one warp per row, 8 rows/block).
// ---------------------------------------------------------------------------
__global__ void kPrep(const float* __restrict__ xq, const float* __restrict__ xs,
                      const int* __restrict__ ys, const int* __restrict__ yq,
                      int Nq, int Ns) {
    if (blockIdx.x == 0) {
        __shared__ int wh[8][C], wqh[8][C];
        __shared__ int cnt[C], off[C], qcnt[C], qoff[C];
        int tid = threadIdx.x, w = tid >> 5;
        for (int i = tid; i < 8 * C; i += 256) { (&wh[0][0])[i] = 0; (&wqh[0][0])[i] = 0; }
        __syncthreads();
        for (int j = tid; j < Ns; j += 256) atomicAdd(&wh[w][ys[j]], 1);
        for (int i = tid; i < Nq; i += 256) atomicAdd(&wqh[w][yq[i]], 1);
        __syncthreads();
        if (tid < C) {
            int s = 0, sq = 0;
#pragma unroll
            for (int r = 0; r < 8; r++) { s += wh[r][tid]; sq += wqh[r][tid]; }
            cnt[tid] = s; qcnt[tid] = sq;
        }
        __syncthreads();
        if (tid == 0) {
            int acc = 0, qacc = 0, nt = 0;
            for (int c = 0; c < C; c++) {
                g_counts[c] = cnt[c]; g_start[c] = acc; off[c] = acc; acc += cnt[c];
                qoff[c] = qacc;
                for (int t = 0; t < qcnt[c]; t += QT) {
                    g_tc[nt] = c; g_toff[nt] = qacc + t;
                    g_tcnt[nt] = min(QT, qcnt[c] - t); nt++;
                }
                qacc += qcnt[c];
            }
            g_start[C] = acc; g_ntiles = nt;
        }
        __syncthreads();
        for (int j = tid; j < Ns; j += 256) { int p = atomicAdd(&off[ys[j]], 1);  g_cidx[p] = j; }
        for (int i = tid; i < Nq; i += 256) { int p = atomicAdd(&qoff[yq[i]], 1); g_qidx[p] = i; }
    } else {
        int warp = (blockIdx.x - 1) * 8 + (threadIdx.x >> 5);
        int lane = threadIdx.x & 31;
        if (warp >= Nq + Ns) return;
        const float4* r4 = (const float4*)((warp < Nq) ? (xq + (size_t)warp * 256)
                                                       : (xs + (size_t)(warp - Nq) * 256));
        float4 a = r4[lane], b = r4[lane + 32];
        float s = a.x*a.x + a.y*a.y + a.z*a.z + a.w*a.w
                + b.x*b.x + b.y*b.y + b.z*b.z + b.w*b.w;
        s = warp_sum(s);
        if (lane == 0) { if (warp < Nq) g_qn[warp] = s; else g_sn[warp - Nq] = s; }
    }
}

// ---------------------------------------------------------------------------
// Kernel 2 (kCent): per-class centroids + sum of member sq-norms.
// Grid (C, 2): block.y owns 128 dims. Also zeroes d_out.
// ---------------------------------------------------------------------------
__global__ void kCent(const float* __restrict__ xs, float* __restrict__ out) {
    int c = blockIdx.x, tid = threadIdx.x;
    if (c == 0 && blockIdx.y == 1 && tid == 0) out[0] = 0.0f;
    int dim = blockIdx.y * 128 + tid;
    int s0 = g_start[c], s1 = g_start[c + 1];
    float acc = 0.0f;
    int m = s0;
    for (; m + 7 < s1; m += 8) {
        float v0 = xs[(size_t)g_cidx[m]   * 256 + dim];
        float v1 = xs[(size_t)g_cidx[m+1] * 256 + dim];
        float v2 = xs[(size_t)g_cidx[m+2] * 256 + dim];
        float v3 = xs[(size_t)g_cidx[m+3] * 256 + dim];
        float v4 = xs[(size_t)g_cidx[m+4] * 256 + dim];
        float v5 = xs[(size_t)g_cidx[m+5] * 256 + dim];
        float v6 = xs[(size_t)g_cidx[m+6] * 256 + dim];
        float v7 = xs[(size_t)g_cidx[m+7] * 256 + dim];
        acc += ((v0 + v1) + (v2 + v3)) + ((v4 + v5) + (v6 + v7));
    }
    for (; m < s1; m++) acc += xs[(size_t)g_cidx[m] * 256 + dim];
    g_cent[c * 256 + dim] = acc;

    if (blockIdx.y == 0) {
        float ss = 0.0f;
        for (int k = s0 + tid; k < s1; k += 128) ss += g_sn[g_cidx[k]];
        __shared__ float sred[128];
        sred[tid] = ss; __syncthreads();
        for (int s = 64; s; s >>= 1) { if (tid < s) sred[tid] += sred[tid + s]; __syncthreads(); }
        if (tid == 0) g_ssum[c] = sred[0];
    }
}

// ---------------------------------------------------------------------------
// Kernel 3 (k_main): 256 threads = 8 warps. Warp w owns queries 4w..4w+3;
// lane owns members 2l,2l+1. 4x2 register tile of f32x2 accumulators.
// Result atomically accumulated into d_out (pre-zeroed by kCent).
// ---------------------------------------------------------------------------
__global__ void __launch_bounds__(256)
k_main(const float* __restrict__ xq, const float* __restrict__ xs,
       const int* __restrict__ pos, float* __restrict__ out, float invNq) {
    int b = blockIdx.x;
    if (b >= g_ntiles) return;

    extern __shared__ float4 dsm[];
    float4* s_q4 = dsm;                  // QT rows x 64 float4
    float4* s_m4 = dsm + QT * D4;        // MB rows x 64 float4, XOR-swizzled
    __shared__ float s_lorig[QT];
    __shared__ float s_msn[MB];
    __shared__ int   s_mj[MB];

    int t = threadIdx.x, w = t >> 5, l = t & 31;
    int c    = g_tc[b];
    int qoff = g_toff[b];
    int qcnt = g_tcnt[b];
    float v  = (g_counts[c] > 1) ? -1000.0f : 0.0f;

    // Load 32 query rows (4 per warp) + metadata.
    float qn[4]; int p[4];
#pragma unroll
    for (int k = 0; k < 4; k++) {
        int ql = 4 * w + k;
        int qi = g_qidx[qoff + min(ql, qcnt - 1)];
        const float4* src = (const float4*)xq + (size_t)qi * D4;
        s_q4[ql * D4 + l]      = src[l];
        s_q4[ql * D4 + l + 32] = src[l + 32];
        qn[k] = g_qn[qi];
        p[k]  = pos[qi];
    }

    int s0 = g_start[c];
    int Mc = g_start[c + 1] - s0;

    float pm[4], ps[4];
#pragma unroll
    for (int k = 0; k < 4; k++) { pm[k] = NEG; ps[k] = 0.0f; }

    const int m0 = 2 * l, m1 = 2 * l + 1;
    const int sig = l & 7;
    const ulonglong2* mr0 = (const ulonglong2*)(s_m4 + m0 * D4);
    const ulonglong2* mr1 = (const ulonglong2*)(s_m4 + m1 * D4);

    // ---- member chunks: positive (in-class) logsumexp ----
    for (int base = 0; base < Mc; base += MB) {
        int nm = min(MB, Mc - base);
        __syncthreads();
        for (int r = 0; r < 8; r++) {
            int m = (r << 3) + w;
            if (m < nm) {
                int j = g_cidx[s0 + base + m];
                int sg = (m >> 1) & 7;
                const float4* src = (const float4*)xs + (size_t)j * D4;
                s_m4[m * D4 + (l ^ sg)]        = src[l];
                s_m4[m * D4 + ((l + 32) ^ sg)] = src[l + 32];
                if (l == 0) { s_mj[m] = j; s_msn[m] = g_sn[j]; }
            } else if (l == 0) s_mj[m] = -1;
        }
        __syncthreads();

        unsigned long long acc[4][2];
#pragma unroll
        for (int k = 0; k < 4; k++) { acc[k][0] = 0ull; acc[k][1] = 0ull; }

#pragma unroll 4
        for (int d = 0; d < D4; d++) {
            int cc = d ^ sig;
            ulonglong2 A = mr0[cc];
            ulonglong2 B = mr1[cc];
#pragma unroll
            for (int k = 0; k < 4; k++) {
                ulonglong2 Q = ((const ulonglong2*)(s_q4 + (4 * w + k) * D4))[d];
                fma2(acc[k][0], Q.x, A.x);
                fma2(acc[k][0], Q.y, A.y);
                fma2(acc[k][1], Q.x, B.x);
                fma2(acc[k][1], Q.y, B.y);
            }
        }

        int   j0 = s_mj[m0],  j1 = s_mj[m1];
        float sn0 = s_msn[m0], sn1 = s_msn[m1];
#pragma unroll
        for (int k = 0; k < 4; k++) {
            float d0 = hsum2(acc[k][0]);
            float d1 = hsum2(acc[k][1]);
            float r0 = -0.5f * fmaxf(qn[k] + sn0 - 2.0f * d0, 0.0f);
            float r1 = -0.5f * fmaxf(qn[k] + sn1 - 2.0f * d1, 0.0f);
            float l0 = (j0 < 0) ? NEG : ((j0 == p[k]) ? v : r0);
            float l1 = (j1 < 0) ? NEG : ((j1 == p[k]) ? v : r1);
            if (j0 >= 0 && j0 == p[k]) s_lorig[4 * w + k] = r0;
            if (j1 >= 0 && j1 == p[k]) s_lorig[4 * w + k] = r1;
            float mx = fmaxf(pm[k], fmaxf(l0, l1));
            if (mx > -1e37f) {
                ps[k] = ps[k] * __expf(pm[k] - mx) + __expf(l0 - mx) + __expf(l1 - mx);
                pm[k] = mx;
            }
        }
    }

    // warp-reduce positive logsumexp
    float posl[4];
#pragma unroll
    for (int k = 0; k < 4; k++) {
        float m = pm[k], s = ps[k];
        for (int o = 16; o; o >>= 1) {
            float om = __shfl_xor_sync(0xffffffffu, m, o);
            float os = __shfl_xor_sync(0xffffffffu, s, o);
            float mx = fmaxf(m, om);
            if (mx > -1e37f) s = s * __expf(m - mx) + os * __expf(om - mx);
            m = mx;
        }
        posl[k] = m + __logf(s);
    }

    // ---- centroid chunk: negative term (closed form + diagonal correction) ----
    __syncthreads();
    for (int r = 0; r < 8; r++) {
        int m = (r << 3) + w;
        int sg = (m >> 1) & 7;
        const float4* src = (const float4*)g_cent + (size_t)m * D4;
        s_m4[m * D4 + (l ^ sg)]        = src[l];
        s_m4[m * D4 + ((l + 32) ^ sg)] = src[l + 32];
    }
    __syncthreads();

    {
        unsigned long long acc[4][2];
#pragma unroll
        for (int k = 0; k < 4; k++) { acc[k][0] = 0ull; acc[k][1] = 0ull; }

#pragma unroll 4
        for (int d = 0; d < D4; d++) {
            int cc = d ^ sig;
            ulonglong2 A = mr0[cc];
            ulonglong2 B = mr1[cc];
#pragma unroll
            for (int k = 0; k < 4; k++) {
                ulonglong2 Q = ((const ulonglong2*)(s_q4 + (4 * w + k) * D4))[d];
                fma2(acc[k][0], Q.x, A.x);
                fma2(acc[k][0], Q.y, A.y);
                fma2(acc[k][1], Q.x, B.x);
                fma2(acc[k][1], Q.y, B.y);
            }
        }

        float cnt0 = (float)g_counts[m0], cnt1 = (float)g_counts[m1];
        float ss0 = g_ssum[m0], ss1 = g_ssum[m1];
        bool  isc0 = (m0 == c), isc1 = (m1 == c);
#pragma unroll
        for (int k = 0; k < 4; k++) {
            float lo = s_lorig[4 * w + k];
            float x0 = -0.5f * (cnt0 * qn[k] + ss0) + hsum2(acc[k][0]);
            float x1 = -0.5f * (cnt1 * qn[k] + ss1) + hsum2(acc[k][1]);
            if (isc0) x0 += v - lo;
            if (isc1) x1 += v - lo;
            x0 /= cnt0 - (isc0 ? 1.0f : 0.0f);
            x1 /= cnt1 - (isc1 ? 1.0f : 0.0f);
            float m = fmaxf(x0, x1);
            float s = __expf(x0 - m) + __expf(x1 - m);
            for (int o = 16; o; o >>= 1) {
                float om = __shfl_xor_sync(0xffffffffu, m, o);
                float os = __shfl_xor_sync(0xffffffffu, s, o);
                float mx = fmaxf(m, om);
                s = s * __expf(m - mx) + os * __expf(om - mx);
                m = mx;
            }
            if (l == 0 && 4 * w + k < qcnt) {
                float neg = m + __logf(s);
                atomicAdd(out, (neg - posl[k]) * invNq);
            }
        }
    }
}

extern "C" void kernel_launch(void* const* d_in, const int* in_sizes, int n_in,
                              void* d_out, int out_size) {
    const float* xq  = (const float*)d_in[0];
    const int*   yq  = (const int*)  d_in[1];
    const float* xs  = (const float*)d_in[2];
    const int*   ys  = (const int*)  d_in[3];
    const int*   pos = (const int*)  d_in[4];
    int Nq = in_sizes[1];
    int Ns = in_sizes[3];

    cudaFuncSetAttribute(k_main, cudaFuncAttributeMaxDynamicSharedMemorySize, SMEM_MAIN);

    int gP = 1 + (Nq + Ns + 7) / 8;
    kPrep<<<gP, 256>>>(xq, xs, ys, yq, Nq, Ns);
    dim3 gc(C, 2);
    kCent<<<gc, 128>>>(xs, (float*)d_out);
    k_main<<<MAXTILES, 256, SMEM_MAIN>>>(xq, xs, pos, (float*)d_out, 1.0f / (float)Nq);
}

// round 6
// speedup vs baseline: 1.2181x; 1.0264x over previous
#include <cuda_runtime.h>
#include <math.h>

#define D4    64            // 256 dims = 64 float4
#define C     64
#define MAXNQ 4096
#define MAXNS 8192
#define QT    32            // queries per tile
#define MB    64            // members per staged chunk
#define MAXTILES (MAXNQ/QT + C)   // 192
#define NEG  (-3.0e38f)
#define SMEM_MAIN ((QT*D4 + MB*D4) * 16)   // 96 KB dynamic

// Scratch (device globals; fully rewritten every call -> replay-safe).
__device__ float g_cent[C * 256];
__device__ float g_ssum[C];
__device__ int   g_counts[C];
__device__ int   g_start[C + 1];
__device__ int   g_cidx[MAXNS];
__device__ int   g_qidx[MAXNQ];
__device__ int   g_tc[MAXTILES], g_toff[MAXTILES], g_tcnt[MAXTILES];
__device__ int   g_ntiles;

__device__ __forceinline__ float warp_sum(float v) {
#pragma unroll
    for (int o = 16; o; o >>= 1) v += __shfl_xor_sync(0xffffffffu, v, o);
    return v;
}

// Packed dual-FMA: d.lo += a.lo*b.lo ; d.hi += a.hi*b.hi   (Blackwell f32x2)
__device__ __forceinline__ void fma2(unsigned long long& d,
                                     unsigned long long a, unsigned long long b) {
    asm("fma.rn.f32x2 %0, %1, %2, %0;" : "+l"(d) : "l"(a), "l"(b));
}
__device__ __forceinline__ float hsum2(unsigned long long v) {
    float lo, hi;
    asm("mov.b64 {%0, %1}, %2;" : "=f"(lo), "=f"(hi) : "l"(v));
    return lo + hi;
}

// ---------------------------------------------------------------------------
// Kernel 1 (kPrep): single CTA. Class lists + tile schedule + zero g_ssum.
// ---------------------------------------------------------------------------
__global__ void kPrep(const int* __restrict__ ys, const int* __restrict__ yq,
                      int Nq, int Ns) {
    __shared__ int wh[8][C], wqh[8][C];
    __shared__ int cnt[C], off[C], qcnt[C], qoff[C];
    int tid = threadIdx.x, w = tid >> 5;
    for (int i = tid; i < 8 * C; i += 256) { (&wh[0][0])[i] = 0; (&wqh[0][0])[i] = 0; }
    if (tid < C) g_ssum[tid] = 0.0f;
    __syncthreads();
    for (int j = tid; j < Ns; j += 256) atomicAdd(&wh[w][ys[j]], 1);
    for (int i = tid; i < Nq; i += 256) atomicAdd(&wqh[w][yq[i]], 1);
    __syncthreads();
    if (tid < C) {
        int s = 0, sq = 0;
#pragma unroll
        for (int r = 0; r < 8; r++) { s += wh[r][tid]; sq += wqh[r][tid]; }
        cnt[tid] = s; qcnt[tid] = sq;
    }
    __syncthreads();
    if (tid == 0) {
        int acc = 0, qacc = 0, nt = 0;
        for (int c = 0; c < C; c++) {
            g_counts[c] = cnt[c]; g_start[c] = acc; off[c] = acc; acc += cnt[c];
            qoff[c] = qacc;
            for (int t = 0; t < qcnt[c]; t += QT) {
                g_tc[nt] = c; g_toff[nt] = qacc + t;
                g_tcnt[nt] = min(QT, qcnt[c] - t); nt++;
            }
            qacc += qcnt[c];
        }
        g_start[C] = acc; g_ntiles = nt;
    }
    __syncthreads();
    for (int j = tid; j < Ns; j += 256) { int p = atomicAdd(&off[ys[j]], 1);  g_cidx[p] = j; }
    for (int i = tid; i < Nq; i += 256) { int p = atomicAdd(&qoff[yq[i]], 1); g_qidx[p] = i; }
}

// ---------------------------------------------------------------------------
// Kernel 2 (kCent): per-class centroids + Sum of member sq-norms (fused:
// accumulates v^2 alongside v; partial per dim-slice, atomicAdd to g_ssum).
// Grid (C, 2): block.y owns 128 dims. Also zeroes d_out.
// ---------------------------------------------------------------------------
__global__ void kCent(const float* __restrict__ xs, float* __restrict__ out) {
    int c = blockIdx.x, tid = threadIdx.x;
    if (c == 0 && blockIdx.y == 1 && tid == 0) out[0] = 0.0f;
    int dim = blockIdx.y * 128 + tid;
    int s0 = g_start[c], s1 = g_start[c + 1];
    float acc = 0.0f, acc2 = 0.0f;
    int m = s0;
    for (; m + 3 < s1; m += 4) {
        float v0 = xs[(size_t)g_cidx[m]   * 256 + dim];
        float v1 = xs[(size_t)g_cidx[m+1] * 256 + dim];
        float v2 = xs[(size_t)g_cidx[m+2] * 256 + dim];
        float v3 = xs[(size_t)g_cidx[m+3] * 256 + dim];
        acc  += (v0 + v1) + (v2 + v3);
        acc2 += (v0*v0 + v1*v1) + (v2*v2 + v3*v3);
    }
    for (; m < s1; m++) {
        float v = xs[(size_t)g_cidx[m] * 256 + dim];
        acc += v; acc2 += v * v;
    }
    g_cent[c * 256 + dim] = acc;

    __shared__ float sred[128];
    sred[tid] = acc2; __syncthreads();
    for (int s = 64; s; s >>= 1) { if (tid < s) sred[tid] += sred[tid + s]; __syncthreads(); }
    if (tid == 0) atomicAdd(&g_ssum[c], sred[0]);
}

// ---------------------------------------------------------------------------
// Kernel 3 (k_main): 256 threads = 8 warps. Warp w owns queries 4w..4w+3;
// lane owns members 2l,2l+1. 4x2 register tile of f32x2 accumulators.
// Row norms computed in-warp at load time (no separate norm pass).
// Per-CTA partial of mean accumulated once into d_out.
// ---------------------------------------------------------------------------
__global__ void __launch_bounds__(256)
k_main(const float* __restrict__ xq, const float* __restrict__ xs,
       const int* __restrict__ pos, float* __restrict__ out, float invNq) {
    int b = blockIdx.x;
    if (b >= g_ntiles) return;

    extern __shared__ float4 dsm[];
    float4* s_q4 = dsm;                  // QT rows x 64 float4
    float4* s_m4 = dsm + QT * D4;        // MB rows x 64 float4, XOR-swizzled
    __shared__ float s_lorig[QT];
    __shared__ float s_msn[MB];
    __shared__ int   s_mj[MB];
    __shared__ float s_res[QT];

    int t = threadIdx.x, w = t >> 5, l = t & 31;
    int c    = g_tc[b];
    int qoff = g_toff[b];
    int qcnt = g_tcnt[b];
    float v  = (g_counts[c] > 1) ? -1000.0f : 0.0f;

    // Load 32 query rows (4 per warp), compute q-norms in-warp, metadata.
    float qn[4]; int p[4];
#pragma unroll
    for (int k = 0; k < 4; k++) {
        int ql = 4 * w + k;
        int qi = g_qidx[qoff + min(ql, qcnt - 1)];
        const float4* src = (const float4*)xq + (size_t)qi * D4;
        float4 a = src[l], bb = src[l + 32];
        s_q4[ql * D4 + l]      = a;
        s_q4[ql * D4 + l + 32] = bb;
        float s = a.x*a.x + a.y*a.y + a.z*a.z + a.w*a.w
                + bb.x*bb.x + bb.y*bb.y + bb.z*bb.z + bb.w*bb.w;
        qn[k] = warp_sum(s);
        p[k]  = pos[qi];
    }

    int s0 = g_start[c];
    int Mc = g_start[c + 1] - s0;

    float pm[4], ps[4];
#pragma unroll
    for (int k = 0; k < 4; k++) { pm[k] = NEG; ps[k] = 0.0f; }

    const int m0 = 2 * l, m1 = 2 * l + 1;
    const int sig = l & 7;
    const ulonglong2* mr0 = (const ulonglong2*)(s_m4 + m0 * D4);
    const ulonglong2* mr1 = (const ulonglong2*)(s_m4 + m1 * D4);

    // ---- member chunks: positive (in-class) logsumexp ----
    for (int base = 0; base < Mc; base += MB) {
        int nm = min(MB, Mc - base);
        __syncthreads();
        for (int r = 0; r < 8; r++) {
            int m = (r << 3) + w;
            if (m < nm) {
                int j = g_cidx[s0 + base + m];
                int sg = (m >> 1) & 7;
                const float4* src = (const float4*)xs + (size_t)j * D4;
                float4 a = src[l], bb = src[l + 32];
                s_m4[m * D4 + (l ^ sg)]        = a;
                s_m4[m * D4 + ((l + 32) ^ sg)] = bb;
                float s = a.x*a.x + a.y*a.y + a.z*a.z + a.w*a.w
                        + bb.x*bb.x + bb.y*bb.y + bb.z*bb.z + bb.w*bb.w;
                s = warp_sum(s);
                if (l == 0) { s_mj[m] = j; s_msn[m] = s; }
            } else if (l == 0) s_mj[m] = -1;
        }
        __syncthreads();

        unsigned long long acc[4][2];
#pragma unroll
        for (int k = 0; k < 4; k++) { acc[k][0] = 0ull; acc[k][1] = 0ull; }

#pragma unroll 4
        for (int d = 0; d < D4; d++) {
            int cc = d ^ sig;
            ulonglong2 A = mr0[cc];
            ulonglong2 B = mr1[cc];
#pragma unroll
            for (int k = 0; k < 4; k++) {
                ulonglong2 Q = ((const ulonglong2*)(s_q4 + (4 * w + k) * D4))[d];
                fma2(acc[k][0], Q.x, A.x);
                fma2(acc[k][0], Q.y, A.y);
                fma2(acc[k][1], Q.x, B.x);
                fma2(acc[k][1], Q.y, B.y);
            }
        }

        int   j0 = s_mj[m0],  j1 = s_mj[m1];
        float sn0 = s_msn[m0], sn1 = s_msn[m1];
#pragma unroll
        for (int k = 0; k < 4; k++) {
            float d0 = hsum2(acc[k][0]);
            float d1 = hsum2(acc[k][1]);
            float r0 = -0.5f * fmaxf(qn[k] + sn0 - 2.0f * d0, 0.0f);
            float r1 = -0.5f * fmaxf(qn[k] + sn1 - 2.0f * d1, 0.0f);
            float l0 = (j0 < 0) ? NEG : ((j0 == p[k]) ? v : r0);
            float l1 = (j1 < 0) ? NEG : ((j1 == p[k]) ? v : r1);
            if (j0 >= 0 && j0 == p[k]) s_lorig[4 * w + k] = r0;
            if (j1 >= 0 && j1 == p[k]) s_lorig[4 * w + k] = r1;
            float mx = fmaxf(pm[k], fmaxf(l0, l1));
            if (mx > -1e37f) {
                ps[k] = ps[k] * __expf(pm[k] - mx) + __expf(l0 - mx) + __expf(l1 - mx);
                pm[k] = mx;
            }
        }
    }

    // warp-reduce positive logsumexp
    float posl[4];
#pragma unroll
    for (int k = 0; k < 4; k++) {
        float m = pm[k], s = ps[k];
        for (int o = 16; o; o >>= 1) {
            float om = __shfl_xor_sync(0xffffffffu, m, o);
            float os = __shfl_xor_sync(0xffffffffu, s, o);
            float mx = fmaxf(m, om);
            if (mx > -1e37f) s = s * __expf(m - mx) + os * __expf(om - mx);
            m = mx;
        }
        posl[k] = m + __logf(s);
    }

    // ---- centroid chunk: negative term (closed form + diagonal correction) ----
    __syncthreads();
    for (int r = 0; r < 8; r++) {
        int m = (r << 3) + w;
        int sg = (m >> 1) & 7;
        const float4* src = (const float4*)g_cent + (size_t)m * D4;
        s_m4[m * D4 + (l ^ sg)]        = src[l];
        s_m4[m * D4 + ((l + 32) ^ sg)] = src[l + 32];
    }
    __syncthreads();

    {
        unsigned long long acc[4][2];
#pragma unroll
        for (int k = 0; k < 4; k++) { acc[k][0] = 0ull; acc[k][1] = 0ull; }

#pragma unroll 4
        for (int d = 0; d < D4; d++) {
            int cc = d ^ sig;
            ulonglong2 A = mr0[cc];
            ulonglong2 B = mr1[cc];
#pragma unroll
            for (int k = 0; k < 4; k++) {
                ulonglong2 Q = ((const ulonglong2*)(s_q4 + (4 * w + k) * D4))[d];
                fma2(acc[k][0], Q.x, A.x);
                fma2(acc[k][0], Q.y, A.y);
                fma2(acc[k][1], Q.x, B.x);
                fma2(acc[k][1], Q.y, B.y);
            }
        }

        float cnt0 = (float)g_counts[m0], cnt1 = (float)g_counts[m1];
        float ss0 = g_ssum[m0], ss1 = g_ssum[m1];
        bool  isc0 = (m0 == c), isc1 = (m1 == c);
#pragma unroll
        for (int k = 0; k < 4; k++) {
            float lo = s_lorig[4 * w + k];
            float x0 = -0.5f * (cnt0 * qn[k] + ss0) + hsum2(acc[k][0]);
            float x1 = -0.5f * (cnt1 * qn[k] + ss1) + hsum2(acc[k][1]);
            if (isc0) x0 += v - lo;
            if (isc1) x1 += v - lo;
            x0 /= cnt0 - (isc0 ? 1.0f : 0.0f);
            x1 /= cnt1 - (isc1 ? 1.0f : 0.0f);
            float m = fmaxf(x0, x1);
            float s = __expf(x0 - m) + __expf(x1 - m);
            for (int o = 16; o; o >>= 1) {
                float om = __shfl_xor_sync(0xffffffffu, m, o);
                float os = __shfl_xor_sync(0xffffffffu, s, o);
                float mx = fmaxf(m, om);
                s = s * __expf(m - mx) + os * __expf(om - mx);
                m = mx;
            }
            if (l == 0) {
                float neg = m + __logf(s);
                s_res[4 * w + k] = (4 * w + k < qcnt) ? (neg - posl[k]) * invNq : 0.0f;
            }
        }
    }

    // per-CTA reduction, single atomic into d_out
    __syncthreads();
    if (w == 0) {
        float a = s_res[l];
        a = warp_sum(a);
        if (l == 0) atomicAdd(out, a);
    }
}

extern "C" void kernel_launch(void* const* d_in, const int* in_sizes, int n_in,
                              void* d_out, int out_size) {
    const float* xq  = (const float*)d_in[0];
    const int*   yq  = (const int*)  d_in[1];
    const float* xs  = (const float*)d_in[2];
    const int*   ys  = (const int*)  d_in[3];
    const int*   pos = (const int*)  d_in[4];
    int Nq = in_sizes[1];
    int Ns = in_sizes[3];

    cudaFuncSetAttribute(k_main, cudaFuncAttributeMaxDynamicSharedMemorySize, SMEM_MAIN);

    kPrep<<<1, 256>>>(ys, yq, Nq, Ns);
    dim3 gc(C, 2);
    kCent<<<gc, 128>>>(xs, (float*)d_out);
    k_main<<<MAXTILES, 256, SMEM_MAIN>>>(xq, xs, pos, (float*)d_out, 1.0f / (float)Nq);
}

// round 7
// speedup vs baseline: 1.2709x; 1.0433x over previous
#include <cuda_runtime.h>
#include <math.h>

#define D4    64            // 256 dims = 64 float4
#define C     64
#define MAXNQ 4096
#define MAXNS 8192
#define QT    32            // queries per tile
#define MB    64            // members per staged chunk
#define MAXTILES (MAXNQ/QT + C)   // 192
#define NEG  (-3.0e38f)
#define SMEM_MAIN ((QT*D4 + MB*D4) * 16)   // 96 KB dynamic

// Scratch (device globals; fully rewritten every call -> replay-safe).
__device__ float g_cent[C * 256];
__device__ float g_ssum[C];
__device__ int   g_counts[C];
__device__ int   g_start[C + 1];
__device__ int   g_cidx[MAXNS];
__device__ int   g_qidx[MAXNQ];
__device__ int   g_tc[MAXTILES], g_toff[MAXTILES], g_tcnt[MAXTILES];
__device__ int   g_ntiles;

__device__ __forceinline__ float warp_sum(float v) {
#pragma unroll
    for (int o = 16; o; o >>= 1) v += __shfl_xor_sync(0xffffffffu, v, o);
    return v;
}

// Packed dual-FMA: d.lo += a.lo*b.lo ; d.hi += a.hi*b.hi   (Blackwell f32x2)
__device__ __forceinline__ void fma2(unsigned long long& d,
                                     unsigned long long a, unsigned long long b) {
    asm("fma.rn.f32x2 %0, %1, %2, %0;" : "+l"(d) : "l"(a), "l"(b));
}
__device__ __forceinline__ float hsum2(unsigned long long v) {
    float lo, hi;
    asm("mov.b64 {%0, %1}, %2;" : "=f"(lo), "=f"(hi) : "l"(v));
    return lo + hi;
}

// ---------------------------------------------------------------------------
// Kernel 1 (kPrep): single CTA, 1024 threads, 4-wide batched loads for MLP.
// Class lists + tile schedule + zero g_cent/g_ssum/d_out.
// ---------------------------------------------------------------------------
__global__ void __launch_bounds__(1024)
kPrep(const int* __restrict__ ys, const int* __restrict__ yq,
      int Nq, int Ns, float* __restrict__ out) {
    __shared__ int wh[32][C], wqh[32][C];
    __shared__ int cnt[C], off[C], qcnt[C], qoff[C];
    int tid = threadIdx.x, w = tid >> 5;
    for (int i = tid; i < 32 * C; i += 1024) { (&wh[0][0])[i] = 0; (&wqh[0][0])[i] = 0; }
    for (int i = tid; i < C * 256; i += 1024) g_cent[i] = 0.0f;
    if (tid < C) g_ssum[tid] = 0.0f;
    if (tid == 0) out[0] = 0.0f;
    __syncthreads();

    // histograms, 4-wide batches
    for (int j = tid; j < Ns; j += 4096) {
        int y0 = ys[j];
        int y1 = (j + 1024 < Ns) ? ys[j + 1024] : -1;
        int y2 = (j + 2048 < Ns) ? ys[j + 2048] : -1;
        int y3 = (j + 3072 < Ns) ? ys[j + 3072] : -1;
        atomicAdd(&wh[w][y0], 1);
        if (y1 >= 0) atomicAdd(&wh[w][y1], 1);
        if (y2 >= 0) atomicAdd(&wh[w][y2], 1);
        if (y3 >= 0) atomicAdd(&wh[w][y3], 1);
    }
    for (int i = tid; i < Nq; i += 4096) {
        int y0 = yq[i];
        int y1 = (i + 1024 < Nq) ? yq[i + 1024] : -1;
        int y2 = (i + 2048 < Nq) ? yq[i + 2048] : -1;
        int y3 = (i + 3072 < Nq) ? yq[i + 3072] : -1;
        atomicAdd(&wqh[w][y0], 1);
        if (y1 >= 0) atomicAdd(&wqh[w][y1], 1);
        if (y2 >= 0) atomicAdd(&wqh[w][y2], 1);
        if (y3 >= 0) atomicAdd(&wqh[w][y3], 1);
    }
    __syncthreads();
    if (tid < C) {
        int s = 0, sq = 0;
#pragma unroll
        for (int r = 0; r < 32; r++) { s += wh[r][tid]; sq += wqh[r][tid]; }
        cnt[tid] = s; qcnt[tid] = sq;
    }
    __syncthreads();
    if (tid == 0) {
        int acc = 0, qacc = 0, nt = 0;
        for (int c = 0; c < C; c++) {
            g_counts[c] = cnt[c]; g_start[c] = acc; off[c] = acc; acc += cnt[c];
            qoff[c] = qacc;
            for (int t = 0; t < qcnt[c]; t += QT) {
                g_tc[nt] = c; g_toff[nt] = qacc + t;
                g_tcnt[nt] = min(QT, qcnt[c] - t); nt++;
            }
            qacc += qcnt[c];
        }
        g_start[C] = acc; g_ntiles = nt;
    }
    __syncthreads();

    // scatter, 4-wide batches
    for (int j = tid; j < Ns; j += 4096) {
        int y0 = ys[j];
        int y1 = (j + 1024 < Ns) ? ys[j + 1024] : -1;
        int y2 = (j + 2048 < Ns) ? ys[j + 2048] : -1;
        int y3 = (j + 3072 < Ns) ? ys[j + 3072] : -1;
        g_cidx[atomicAdd(&off[y0], 1)] = j;
        if (y1 >= 0) g_cidx[atomicAdd(&off[y1], 1)] = j + 1024;
        if (y2 >= 0) g_cidx[atomicAdd(&off[y2], 1)] = j + 2048;
        if (y3 >= 0) g_cidx[atomicAdd(&off[y3], 1)] = j + 3072;
    }
    for (int i = tid; i < Nq; i += 4096) {
        int y0 = yq[i];
        int y1 = (i + 1024 < Nq) ? yq[i + 1024] : -1;
        int y2 = (i + 2048 < Nq) ? yq[i + 2048] : -1;
        int y3 = (i + 3072 < Nq) ? yq[i + 3072] : -1;
        g_qidx[atomicAdd(&qoff[y0], 1)] = i;
        if (y1 >= 0) g_qidx[atomicAdd(&qoff[y1], 1)] = i + 1024;
        if (y2 >= 0) g_qidx[atomicAdd(&qoff[y2], 1)] = i + 2048;
        if (y3 >= 0) g_qidx[atomicAdd(&qoff[y3], 1)] = i + 3072;
    }
}

// ---------------------------------------------------------------------------
// Kernel 2 (kCent): partial centroids + partial sq-norm sums.
// Grid (C, 2, 4): y = dim half, z = member quarter. atomicAdd into zeroed
// g_cent / g_ssum. 512 CTAs -> full-chip MLP for the scattered row gather.
// ---------------------------------------------------------------------------
__global__ void kCent(const float* __restrict__ xs) {
    int c = blockIdx.x, tid = threadIdx.x;
    int dim = blockIdx.y * 128 + tid;
    int s0 = g_start[c], s1 = g_start[c + 1];
    int Mc = s1 - s0;
    int b0 = s0 + (Mc * (int)blockIdx.z) / 4;
    int b1 = s0 + (Mc * ((int)blockIdx.z + 1)) / 4;
    float acc = 0.0f, acc2 = 0.0f;
    int m = b0;
    for (; m + 3 < b1; m += 4) {
        float v0 = xs[(size_t)g_cidx[m]   * 256 + dim];
        float v1 = xs[(size_t)g_cidx[m+1] * 256 + dim];
        float v2 = xs[(size_t)g_cidx[m+2] * 256 + dim];
        float v3 = xs[(size_t)g_cidx[m+3] * 256 + dim];
        acc  += (v0 + v1) + (v2 + v3);
        acc2 += (v0*v0 + v1*v1) + (v2*v2 + v3*v3);
    }
    for (; m < b1; m++) {
        float v = xs[(size_t)g_cidx[m] * 256 + dim];
        acc += v; acc2 += v * v;
    }
    atomicAdd(&g_cent[c * 256 + dim], acc);

    __shared__ float sred[128];
    sred[tid] = acc2; __syncthreads();
    for (int s = 64; s; s >>= 1) { if (tid < s) sred[tid] += sred[tid + s]; __syncthreads(); }
    if (tid == 0 && blockIdx.y == 0) atomicAdd(&g_ssum[c], sred[0]);
    if (tid == 1 && blockIdx.y == 1) atomicAdd(&g_ssum[c], sred[0]);
}

// ---------------------------------------------------------------------------
// Kernel 3 (k_main): unchanged from R6 (passing). 256 threads = 8 warps.
// Warp w owns queries 4w..4w+3; lane owns members 2l,2l+1. f32x2 accums.
// ---------------------------------------------------------------------------
__global__ void __launch_bounds__(256)
k_main(const float* __restrict__ xq, const float* __restrict__ xs,
       const int* __restrict__ pos, float* __restrict__ out, float invNq) {
    int b = blockIdx.x;
    if (b >= g_ntiles) return;

    extern __shared__ float4 dsm[];
    float4* s_q4 = dsm;                  // QT rows x 64 float4
    float4* s_m4 = dsm + QT * D4;        // MB rows x 64 float4, XOR-swizzled
    __shared__ float s_lorig[QT];
    __shared__ float s_msn[MB];
    __shared__ int   s_mj[MB];
    __shared__ float s_res[QT];

    int t = threadIdx.x, w = t >> 5, l = t & 31;
    int c    = g_tc[b];
    int qoff = g_toff[b];
    int qcnt = g_tcnt[b];
    float v  = (g_counts[c] > 1) ? -1000.0f : 0.0f;

    float qn[4]; int p[4];
#pragma unroll
    for (int k = 0; k < 4; k++) {
        int ql = 4 * w + k;
        int qi = g_qidx[qoff + min(ql, qcnt - 1)];
        const float4* src = (const float4*)xq + (size_t)qi * D4;
        float4 a = src[l], bb = src[l + 32];
        s_q4[ql * D4 + l]      = a;
        s_q4[ql * D4 + l + 32] = bb;
        float s = a.x*a.x + a.y*a.y + a.z*a.z + a.w*a.w
                + bb.x*bb.x + bb.y*bb.y + bb.z*bb.z + bb.w*bb.w;
        qn[k] = warp_sum(s);
        p[k]  = pos[qi];
    }

    int s0 = g_start[c];
    int Mc = g_start[c + 1] - s0;

    float pm[4], ps[4];
#pragma unroll
    for (int k = 0; k < 4; k++) { pm[k] = NEG; ps[k] = 0.0f; }

    const int m0 = 2 * l, m1 = 2 * l + 1;
    const int sig = l & 7;
    const ulonglong2* mr0 = (const ulonglong2*)(s_m4 + m0 * D4);
    const ulonglong2* mr1 = (const ulonglong2*)(s_m4 + m1 * D4);

    for (int base = 0; base < Mc; base += MB) {
        int nm = min(MB, Mc - base);
        __syncthreads();
        for (int r = 0; r < 8; r++) {
            int m = (r << 3) + w;
            if (m < nm) {
                int j = g_cidx[s0 + base + m];
                int sg = (m >> 1) & 7;
                const float4* src = (const float4*)xs + (size_t)j * D4;
                float4 a = src[l], bb = src[l + 32];
                s_m4[m * D4 + (l ^ sg)]        = a;
                s_m4[m * D4 + ((l + 32) ^ sg)] = bb;
                float s = a.x*a.x + a.y*a.y + a.z*a.z + a.w*a.w
                        + bb.x*bb.x + bb.y*bb.y + bb.z*bb.z + bb.w*bb.w;
                s = warp_sum(s);
                if (l == 0) { s_mj[m] = j; s_msn[m] = s; }
            } else if (l == 0) s_mj[m] = -1;
        }
        __syncthreads();

        unsigned long long acc[4][2];
#pragma unroll
        for (int k = 0; k < 4; k++) { acc[k][0] = 0ull; acc[k][1] = 0ull; }

#pragma unroll 4
        for (int d = 0; d < D4; d++) {
            int cc = d ^ sig;
            ulonglong2 A = mr0[cc];
            ulonglong2 B = mr1[cc];
#pragma unroll
            for (int k = 0; k < 4; k++) {
                ulonglong2 Q = ((const ulonglong2*)(s_q4 + (4 * w + k) * D4))[d];
                fma2(acc[k][0], Q.x, A.x);
                fma2(acc[k][0], Q.y, A.y);
                fma2(acc[k][1], Q.x, B.x);
                fma2(acc[k][1], Q.y, B.y);
            }
        }

        int   j0 = s_mj[m0],  j1 = s_mj[m1];
        float sn0 = s_msn[m0], sn1 = s_msn[m1];
#pragma unroll
        for (int k = 0; k < 4; k++) {
            float d0 = hsum2(acc[k][0]);
            float d1 = hsum2(acc[k][1]);
            float r0 = -0.5f * fmaxf(qn[k] + sn0 - 2.0f * d0, 0.0f);
            float r1 = -0.5f * fmaxf(qn[k] + sn1 - 2.0f * d1, 0.0f);
            float l0 = (j0 < 0) ? NEG : ((j0 == p[k]) ? v : r0);
            float l1 = (j1 < 0) ? NEG : ((j1 == p[k]) ? v : r1);
            if (j0 >= 0 && j0 == p[k]) s_lorig[4 * w + k] = r0;
            if (j1 >= 0 && j1 == p[k]) s_lorig[4 * w + k] = r1;
            float mx = fmaxf(pm[k], fmaxf(l0, l1));
            if (mx > -1e37f) {
                ps[k] = ps[k] * __expf(pm[k] - mx) + __expf(l0 - mx) + __expf(l1 - mx);
                pm[k] = mx;
            }
        }
    }

    float posl[4];
#pragma unroll
    for (int k = 0; k < 4; k++) {
        float m = pm[k], s = ps[k];
        for (int o = 16; o; o >>= 1) {
            float om = __shfl_xor_sync(0xffffffffu, m, o);
            float os = __shfl_xor_sync(0xffffffffu, s, o);
            float mx = fmaxf(m, om);
            if (mx > -1e37f) s = s * __expf(m - mx) + os * __expf(om - mx);
            m = mx;
        }
        posl[k] = m + __logf(s);
    }

    __syncthreads();
    for (int r = 0; r < 8; r++) {
        int m = (r << 3) + w;
        int sg = (m >> 1) & 7;
        const float4* src = (const float4*)g_cent + (size_t)m * D4;
        s_m4[m * D4 + (l ^ sg)]        = src[l];
        s_m4[m * D4 + ((l + 32) ^ sg)] = src[l + 32];
    }
    __syncthreads();

    {
        unsigned long long acc[4][2];
#pragma unroll
        for (int k = 0; k < 4; k++) { acc[k][0] = 0ull; acc[k][1] = 0ull; }

#pragma unroll 4
        for (int d = 0; d < D4; d++) {
            int cc = d ^ sig;
            ulonglong2 A = mr0[cc];
            ulonglong2 B = mr1[cc];
#pragma unroll
            for (int k = 0; k < 4; k++) {
                ulonglong2 Q = ((const ulonglong2*)(s_q4 + (4 * w + k) * D4))[d];
                fma2(acc[k][0], Q.x, A.x);
                fma2(acc[k][0], Q.y, A.y);
                fma2(acc[k][1], Q.x, B.x);
                fma2(acc[k][1], Q.y, B.y);
            }
        }

        float cnt0 = (float)g_counts[m0], cnt1 = (float)g_counts[m1];
        float ss0 = g_ssum[m0], ss1 = g_ssum[m1];
        bool  isc0 = (m0 == c), isc1 = (m1 == c);
#pragma unroll
        for (int k = 0; k < 4; k++) {
            float lo = s_lorig[4 * w + k];
            float x0 = -0.5f * (cnt0 * qn[k] + ss0) + hsum2(acc[k][0]);
            float x1 = -0.5f * (cnt1 * qn[k] + ss1) + hsum2(acc[k][1]);
            if (isc0) x0 += v - lo;
            if (isc1) x1 += v - lo;
            x0 /= cnt0 - (isc0 ? 1.0f : 0.0f);
            x1 /= cnt1 - (isc1 ? 1.0f : 0.0f);
            float m = fmaxf(x0, x1);
            float s = __expf(x0 - m) + __expf(x1 - m);
            for (int o = 16; o; o >>= 1) {
                float om = __shfl_xor_sync(0xffffffffu, m, o);
                float os = __shfl_xor_sync(0xffffffffu, s, o);
                float mx = fmaxf(m, om);
                s = s * __expf(m - mx) + os * __expf(om - mx);
                m = mx;
            }
            if (l == 0) {
                float neg = m + __logf(s);
                s_res[4 * w + k] = (4 * w + k < qcnt) ? (neg - posl[k]) * invNq : 0.0f;
            }
        }
    }

    __syncthreads();
    if (w == 0) {
        float a = s_res[l];
        a = warp_sum(a);
        if (l == 0) atomicAdd(out, a);
    }
}

extern "C" void kernel_launch(void* const* d_in, const int* in_sizes, int n_in,
                              void* d_out, int out_size) {
    const float* xq  = (const float*)d_in[0];
    const int*   yq  = (const int*)  d_in[1];
    const float* xs  = (const float*)d_in[2];
    const int*   ys  = (const int*)  d_in[3];
    const int*   pos = (const int*)  d_in[4];
    int Nq = in_sizes[1];
    int Ns = in_sizes[3];

    cudaFuncSetAttribute(k_main, cudaFuncAttributeMaxDynamicSharedMemorySize, SMEM_MAIN);

    kPrep<<<1, 1024>>>(ys, yq, Nq, Ns, (float*)d_out);
    dim3 gc(C, 2, 4);
    kCent<<<gc, 128>>>(xs);
    k_main<<<MAXTILES, 256, SMEM_MAIN>>>(xq, xs, pos, (float*)d_out, 1.0f / (float)Nq);
}